// round 10
// baseline (speedup 1.0000x reference)
#include <cuda_runtime.h>
#include <cuda_bf16.h>
#include <stdint.h>

#define NUM_USERS 100000
#define NUM_ITEMS 50000
#define N_NODES   (NUM_USERS + NUM_ITEMS)   // 150000
#define EMBED_DIM 64
#define N_EDGES   1000000

#define SCAN_BS   1024
#define N_SCAN_BLOCKS ((N_NODES + SCAN_BS - 1) / SCAN_BS)   // 147

#define A_FLAG (1u << 30)
#define P_FLAG (1u << 31)
#define VAL_MASK 0x3FFFFFFFu

// ---- static device scratch (no allocation allowed) ----
__device__ int      g_deg[N_NODES];
__device__ float    g_dinv[N_NODES];
__device__ int      g_off[N_NODES];        // excl prefix -> end offsets after scatter
__device__ unsigned g_part[N_SCAN_BLOCKS]; // lookback state (reset each call)
__device__ int2     g_csr[N_EDGES];        // {src, norm_bits}
__device__ float    g_x1[N_NODES * EMBED_DIM];
__device__ float    g_x2[N_NODES * EMBED_DIM];

// -------------------- setup kernels --------------------

__global__ void k_degree(const int* __restrict__ edge_index) {
    int e = blockIdx.x * blockDim.x + threadIdx.x;
    if (e < N_EDGES) atomicAdd(&g_deg[edge_index[N_EDGES + e]], 1);
}

// single-pass decoupled-lookback exclusive scan of degrees; also emits dinv.
__global__ void __launch_bounds__(SCAN_BS) k_scan() {
    __shared__ int s_wt[32];
    __shared__ int s_run;

    int tid  = threadIdx.x;
    int bid  = blockIdx.x;
    int lane = tid & 31;
    int wid  = tid >> 5;
    int i    = bid * SCAN_BS + tid;

    int v = (i < N_NODES) ? g_deg[i] : 0;
    if (i < N_NODES) g_dinv[i] = (v > 0) ? rsqrtf((float)v) : 0.0f;

    int inc = v;
    #pragma unroll
    for (int d = 1; d < 32; d <<= 1) {
        int t = __shfl_up_sync(0xffffffffu, inc, d);
        if (lane >= d) inc += t;
    }
    if (lane == 31) s_wt[wid] = inc;
    __syncthreads();

    if (wid == 0) {
        int wv = s_wt[lane];
        int winc = wv;
        #pragma unroll
        for (int d = 1; d < 32; d <<= 1) {
            int t = __shfl_up_sync(0xffffffffu, winc, d);
            if (lane >= d) winc += t;
        }
        s_wt[lane] = winc;
        if (lane == 31)
            atomicExch(&g_part[bid], A_FLAG | (unsigned)winc);

        int running = 0;
        int look = bid - 1;
        while (look >= 0) {
            int idx = look - lane;
            unsigned w;
            if (idx >= 0) {
                volatile unsigned* p = (volatile unsigned*)&g_part[idx];
                do { w = *p; } while ((w & (A_FLAG | P_FLAG)) == 0);
            } else {
                w = P_FLAG;
            }
            unsigned pm = __ballot_sync(0xffffffffu, (w & P_FLAG) != 0);
            int firstP = pm ? (__ffs(pm) - 1) : 32;
            int contrib = (lane <= firstP) ? (int)(w & VAL_MASK) : 0;
            #pragma unroll
            for (int d = 16; d; d >>= 1) contrib += __shfl_down_sync(0xffffffffu, contrib, d);
            contrib = __shfl_sync(0xffffffffu, contrib, 0);
            running += contrib;
            if (firstP < 32) break;
            look -= 32;
        }
        if (lane == 31)
            atomicExch(&g_part[bid], P_FLAG | (unsigned)(running + winc));
        if (lane == 0) s_run = running;
    }
    __syncthreads();

    int excl = (wid ? s_wt[wid - 1] : 0) + (inc - v) + s_run;
    if (i < N_NODES) g_off[i] = excl;
}

// scatter edges into CSR-by-dst; single atomic bumps g_off[dst] itself.
__global__ void k_scatter(const int* __restrict__ edge_index) {
    int e = blockIdx.x * blockDim.x + threadIdx.x;
    if (e < N_EDGES) {
        int src = edge_index[e];
        int dst = edge_index[N_EDGES + e];
        int pos = atomicAdd(&g_off[dst], 1);
        float norm = g_dinv[src] * g_dinv[dst];
        g_csr[pos] = make_int2(src, __float_as_int(norm));
    }
}

// -------------------- propagation --------------------
// 4 nodes per warp: 8 lanes per node, 2 x float4 per lane (8 x 32B = 256B row).
// Branchless batches of 4 edges (clamped index, zeroed weight): 8 independent
// LDG.128 in flight per node-group per trip.
__device__ __forceinline__ void gather_node8(const float4* __restrict__ xin,
                                             int beg, int end, int q0, int q1,
                                             float4& sa, float4& sb) {
    sa = make_float4(0.0f, 0.0f, 0.0f, 0.0f);
    sb = make_float4(0.0f, 0.0f, 0.0f, 0.0f);
    int last = end - 1;
    for (int e = beg; e < end; e += 4) {
        int i1 = min(e + 1, last);
        int i2 = min(e + 2, last);
        int i3 = min(e + 3, last);
        int2 p0 = g_csr[e];
        int2 p1 = g_csr[i1];
        int2 p2 = g_csr[i2];
        int2 p3 = g_csr[i3];
        size_t r0 = (size_t)p0.x * 16, r1 = (size_t)p1.x * 16;
        size_t r2 = (size_t)p2.x * 16, r3 = (size_t)p3.x * 16;
        float4 a0 = xin[r0 + q0];  float4 b0 = xin[r0 + q1];
        float4 a1 = xin[r1 + q0];  float4 b1 = xin[r1 + q1];
        float4 a2 = xin[r2 + q0];  float4 b2 = xin[r2 + q1];
        float4 a3 = xin[r3 + q0];  float4 b3 = xin[r3 + q1];
        float w0 = __int_as_float(p0.y);
        float w1 = (e + 1 < end) ? __int_as_float(p1.y) : 0.0f;
        float w2 = (e + 2 < end) ? __int_as_float(p2.y) : 0.0f;
        float w3 = (e + 3 < end) ? __int_as_float(p3.y) : 0.0f;
        sa.x = fmaf(a0.x, w0, sa.x);  sa.y = fmaf(a0.y, w0, sa.y);
        sa.z = fmaf(a0.z, w0, sa.z);  sa.w = fmaf(a0.w, w0, sa.w);
        sb.x = fmaf(b0.x, w0, sb.x);  sb.y = fmaf(b0.y, w0, sb.y);
        sb.z = fmaf(b0.z, w0, sb.z);  sb.w = fmaf(b0.w, w0, sb.w);
        sa.x = fmaf(a1.x, w1, sa.x);  sa.y = fmaf(a1.y, w1, sa.y);
        sa.z = fmaf(a1.z, w1, sa.z);  sa.w = fmaf(a1.w, w1, sa.w);
        sb.x = fmaf(b1.x, w1, sb.x);  sb.y = fmaf(b1.y, w1, sb.y);
        sb.z = fmaf(b1.z, w1, sb.z);  sb.w = fmaf(b1.w, w1, sb.w);
        sa.x = fmaf(a2.x, w2, sa.x);  sa.y = fmaf(a2.y, w2, sa.y);
        sa.z = fmaf(a2.z, w2, sa.z);  sa.w = fmaf(a2.w, w2, sa.w);
        sb.x = fmaf(b2.x, w2, sb.x);  sb.y = fmaf(b2.y, w2, sb.y);
        sb.z = fmaf(b2.z, w2, sb.z);  sb.w = fmaf(b2.w, w2, sb.w);
        sa.x = fmaf(a3.x, w3, sa.x);  sa.y = fmaf(a3.y, w3, sa.y);
        sa.z = fmaf(a3.z, w3, sa.z);  sa.w = fmaf(a3.w, w3, sa.w);
        sb.x = fmaf(b3.x, w3, sb.x);  sb.y = fmaf(b3.y, w3, sb.y);
        sb.z = fmaf(b3.z, w3, sb.z);  sb.w = fmaf(b3.w, w3, sb.w);
    }
}

// shifted-offset convention: end = g_off[node], beg = node ? g_off[node-1] : 0
__global__ void __launch_bounds__(256) k_prop1(const float4* __restrict__ emb) {
    int gtid = blockIdx.x * blockDim.x + threadIdx.x;
    int node = gtid >> 3, olane = gtid & 7;
    if (node >= N_NODES) return;
    int end = g_off[node];
    int beg = node ? g_off[node - 1] : 0;
    int q0 = olane * 2, q1 = q0 + 1;
    float4 sa, sb;
    gather_node8(emb, beg, end, q0, q1, sa, sb);
    ((float4*)g_x1)[(size_t)node * 16 + q0] = sa;
    ((float4*)g_x1)[(size_t)node * 16 + q1] = sb;
}

__global__ void __launch_bounds__(256) k_prop2() {
    int gtid = blockIdx.x * blockDim.x + threadIdx.x;
    int node = gtid >> 3, olane = gtid & 7;
    if (node >= N_NODES) return;
    int end = g_off[node];
    int beg = node ? g_off[node - 1] : 0;
    int q0 = olane * 2, q1 = q0 + 1;
    float4 sa, sb;
    gather_node8((const float4*)g_x1, beg, end, q0, q1, sa, sb);
    ((float4*)g_x2)[(size_t)node * 16 + q0] = sa;
    ((float4*)g_x2)[(size_t)node * 16 + q1] = sb;
}

// layer 3 + epilogue: out = 0.25*(emb + l1 + l2 + A~*l2)
__global__ void __launch_bounds__(256) k_prop_last(const float4* __restrict__ emb,
                                                   float4* __restrict__ out) {
    int gtid = blockIdx.x * blockDim.x + threadIdx.x;
    int node = gtid >> 3, olane = gtid & 7;
    if (node >= N_NODES) return;
    int end = g_off[node];
    int beg = node ? g_off[node - 1] : 0;
    int q0 = olane * 2, q1 = q0 + 1;
    float4 sa, sb;
    gather_node8((const float4*)g_x2, beg, end, q0, q1, sa, sb);

    size_t oi = (size_t)node * 16;
    float4 e0 = emb[oi + q0];
    float4 e1 = emb[oi + q1];
    float4 x1a = ((const float4*)g_x1)[oi + q0];
    float4 x1b = ((const float4*)g_x1)[oi + q1];
    float4 x2a = ((const float4*)g_x2)[oi + q0];
    float4 x2b = ((const float4*)g_x2)[oi + q1];
    float4 oa, ob;
    oa.x = 0.25f * (e0.x + x1a.x + x2a.x + sa.x);
    oa.y = 0.25f * (e0.y + x1a.y + x2a.y + sa.y);
    oa.z = 0.25f * (e0.z + x1a.z + x2a.z + sa.z);
    oa.w = 0.25f * (e0.w + x1a.w + x2a.w + sa.w);
    ob.x = 0.25f * (e1.x + x1b.x + x2b.x + sb.x);
    ob.y = 0.25f * (e1.y + x1b.y + x2b.y + sb.y);
    ob.z = 0.25f * (e1.z + x1b.z + x2b.z + sb.z);
    ob.w = 0.25f * (e1.w + x1b.w + x2b.w + sb.w);
    out[oi + q0] = oa;
    out[oi + q1] = ob;
}

// -------------------- launch --------------------

extern "C" void kernel_launch(void* const* d_in, const int* in_sizes, int n_in,
                              void* d_out, int out_size) {
    const int*   edge_index = (const int*)d_in[0];     // int32
    const float* emb_weight = (const float*)d_in[1];
    float*       out        = (float*)d_out;

    void* deg_ptr = nullptr;  cudaGetSymbolAddress(&deg_ptr, g_deg);
    void* part_ptr = nullptr; cudaGetSymbolAddress(&part_ptr, g_part);
    cudaMemsetAsync(deg_ptr, 0, N_NODES * sizeof(int), 0);
    cudaMemsetAsync(part_ptr, 0, N_SCAN_BLOCKS * sizeof(unsigned), 0);

    const int BS = 256;
    int ge = (N_EDGES + BS - 1) / BS;

    k_degree<<<ge, BS>>>(edge_index);                // kernel 1
    k_scan<<<N_SCAN_BLOCKS, SCAN_BS>>>();            // kernel 2
    k_scatter<<<ge, BS>>>(edge_index);               // kernel 3

    int gp = (N_NODES * 8 + BS - 1) / BS;            // 8 threads per node
    k_prop1<<<gp, BS>>>((const float4*)emb_weight);            // kernel 4 <- ncu
    k_prop2<<<gp, BS>>>();                                     // kernel 5
    k_prop_last<<<gp, BS>>>((const float4*)emb_weight, (float4*)out); // kernel 6
}

// round 11
// speedup vs baseline: 1.0554x; 1.0554x over previous
#include <cuda_runtime.h>
#include <cuda_bf16.h>
#include <stdint.h>

#define NUM_USERS 100000
#define NUM_ITEMS 50000
#define N_NODES   (NUM_USERS + NUM_ITEMS)   // 150000
#define EMBED_DIM 64
#define N_EDGES   1000000

#define SCAN_BS   1024
#define N_SCAN_BLOCKS ((N_NODES + SCAN_BS - 1) / SCAN_BS)   // 147

#define A_FLAG (1u << 30)
#define P_FLAG (1u << 31)
#define VAL_MASK 0x3FFFFFFFu

// ---- static device scratch (no allocation allowed) ----
__device__ int      g_deg[N_NODES];
__device__ float    g_dinv[N_NODES];
__device__ int      g_off[N_NODES];        // excl prefix -> end offsets after scatter
__device__ unsigned g_part[N_SCAN_BLOCKS]; // lookback state (reset each call)
__device__ int2     g_csr[N_EDGES];        // {src, norm_bits}
__device__ float    g_x1[N_NODES * EMBED_DIM];
__device__ float    g_x2[N_NODES * EMBED_DIM];

// -------------------- setup kernels --------------------

__global__ void k_degree(const int* __restrict__ edge_index) {
    int e = blockIdx.x * blockDim.x + threadIdx.x;
    if (e < N_EDGES) atomicAdd(&g_deg[edge_index[N_EDGES + e]], 1);
}

// single-pass decoupled-lookback exclusive scan of degrees; also emits dinv.
__global__ void __launch_bounds__(SCAN_BS) k_scan() {
    __shared__ int s_wt[32];
    __shared__ int s_run;

    int tid  = threadIdx.x;
    int bid  = blockIdx.x;
    int lane = tid & 31;
    int wid  = tid >> 5;
    int i    = bid * SCAN_BS + tid;

    int v = (i < N_NODES) ? g_deg[i] : 0;
    if (i < N_NODES) g_dinv[i] = (v > 0) ? rsqrtf((float)v) : 0.0f;

    int inc = v;
    #pragma unroll
    for (int d = 1; d < 32; d <<= 1) {
        int t = __shfl_up_sync(0xffffffffu, inc, d);
        if (lane >= d) inc += t;
    }
    if (lane == 31) s_wt[wid] = inc;
    __syncthreads();

    if (wid == 0) {
        int wv = s_wt[lane];
        int winc = wv;
        #pragma unroll
        for (int d = 1; d < 32; d <<= 1) {
            int t = __shfl_up_sync(0xffffffffu, winc, d);
            if (lane >= d) winc += t;
        }
        s_wt[lane] = winc;
        if (lane == 31)
            atomicExch(&g_part[bid], A_FLAG | (unsigned)winc);

        int running = 0;
        int look = bid - 1;
        while (look >= 0) {
            int idx = look - lane;
            unsigned w;
            if (idx >= 0) {
                volatile unsigned* p = (volatile unsigned*)&g_part[idx];
                do { w = *p; } while ((w & (A_FLAG | P_FLAG)) == 0);
            } else {
                w = P_FLAG;
            }
            unsigned pm = __ballot_sync(0xffffffffu, (w & P_FLAG) != 0);
            int firstP = pm ? (__ffs(pm) - 1) : 32;
            int contrib = (lane <= firstP) ? (int)(w & VAL_MASK) : 0;
            #pragma unroll
            for (int d = 16; d; d >>= 1) contrib += __shfl_down_sync(0xffffffffu, contrib, d);
            contrib = __shfl_sync(0xffffffffu, contrib, 0);
            running += contrib;
            if (firstP < 32) break;
            look -= 32;
        }
        if (lane == 31)
            atomicExch(&g_part[bid], P_FLAG | (unsigned)(running + winc));
        if (lane == 0) s_run = running;
    }
    __syncthreads();

    int excl = (wid ? s_wt[wid - 1] : 0) + (inc - v) + s_run;
    if (i < N_NODES) g_off[i] = excl;
}

// scatter edges into CSR-by-dst; single atomic bumps g_off[dst] itself.
__global__ void k_scatter(const int* __restrict__ edge_index) {
    int e = blockIdx.x * blockDim.x + threadIdx.x;
    if (e < N_EDGES) {
        int src = edge_index[e];
        int dst = edge_index[N_EDGES + e];
        int pos = atomicAdd(&g_off[dst], 1);
        float norm = g_dinv[src] * g_dinv[dst];
        g_csr[pos] = make_int2(src, __float_as_int(norm));
    }
}

// -------------------- propagation --------------------
// 4 nodes per warp: 8 lanes per node, 2 x float4 per lane.
// Lane addressing is LINE-CONTIGUOUS: q0 = olane (bytes [0,128) of the row),
// q1 = olane + 8 (bytes [128,256)). Each warp-level load covers whole 128B
// lines (4 wavefronts / 512B) while keeping 8 independent LDG.128 per trip.
// Branchless batches of 4 edges (clamped index, zeroed weight).
__device__ __forceinline__ void gather_node8(const float4* __restrict__ xin,
                                             int beg, int end, int q0, int q1,
                                             float4& sa, float4& sb) {
    sa = make_float4(0.0f, 0.0f, 0.0f, 0.0f);
    sb = make_float4(0.0f, 0.0f, 0.0f, 0.0f);
    int last = end - 1;
    for (int e = beg; e < end; e += 4) {
        int i1 = min(e + 1, last);
        int i2 = min(e + 2, last);
        int i3 = min(e + 3, last);
        int2 p0 = g_csr[e];
        int2 p1 = g_csr[i1];
        int2 p2 = g_csr[i2];
        int2 p3 = g_csr[i3];
        size_t r0 = (size_t)p0.x * 16, r1 = (size_t)p1.x * 16;
        size_t r2 = (size_t)p2.x * 16, r3 = (size_t)p3.x * 16;
        float4 a0 = xin[r0 + q0];  float4 b0 = xin[r0 + q1];
        float4 a1 = xin[r1 + q0];  float4 b1 = xin[r1 + q1];
        float4 a2 = xin[r2 + q0];  float4 b2 = xin[r2 + q1];
        float4 a3 = xin[r3 + q0];  float4 b3 = xin[r3 + q1];
        float w0 = __int_as_float(p0.y);
        float w1 = (e + 1 < end) ? __int_as_float(p1.y) : 0.0f;
        float w2 = (e + 2 < end) ? __int_as_float(p2.y) : 0.0f;
        float w3 = (e + 3 < end) ? __int_as_float(p3.y) : 0.0f;
        sa.x = fmaf(a0.x, w0, sa.x);  sa.y = fmaf(a0.y, w0, sa.y);
        sa.z = fmaf(a0.z, w0, sa.z);  sa.w = fmaf(a0.w, w0, sa.w);
        sb.x = fmaf(b0.x, w0, sb.x);  sb.y = fmaf(b0.y, w0, sb.y);
        sb.z = fmaf(b0.z, w0, sb.z);  sb.w = fmaf(b0.w, w0, sb.w);
        sa.x = fmaf(a1.x, w1, sa.x);  sa.y = fmaf(a1.y, w1, sa.y);
        sa.z = fmaf(a1.z, w1, sa.z);  sa.w = fmaf(a1.w, w1, sa.w);
        sb.x = fmaf(b1.x, w1, sb.x);  sb.y = fmaf(b1.y, w1, sb.y);
        sb.z = fmaf(b1.z, w1, sb.z);  sb.w = fmaf(b1.w, w1, sb.w);
        sa.x = fmaf(a2.x, w2, sa.x);  sa.y = fmaf(a2.y, w2, sa.y);
        sa.z = fmaf(a2.z, w2, sa.z);  sa.w = fmaf(a2.w, w2, sa.w);
        sb.x = fmaf(b2.x, w2, sb.x);  sb.y = fmaf(b2.y, w2, sb.y);
        sb.z = fmaf(b2.z, w2, sb.z);  sb.w = fmaf(b2.w, w2, sb.w);
        sa.x = fmaf(a3.x, w3, sa.x);  sa.y = fmaf(a3.y, w3, sa.y);
        sa.z = fmaf(a3.z, w3, sa.z);  sa.w = fmaf(a3.w, w3, sa.w);
        sb.x = fmaf(b3.x, w3, sb.x);  sb.y = fmaf(b3.y, w3, sb.y);
        sb.z = fmaf(b3.z, w3, sb.z);  sb.w = fmaf(b3.w, w3, sb.w);
    }
}

// shifted-offset convention: end = g_off[node], beg = node ? g_off[node-1] : 0
__global__ void __launch_bounds__(256) k_prop1(const float4* __restrict__ emb) {
    int gtid = blockIdx.x * blockDim.x + threadIdx.x;
    int node = gtid >> 3, olane = gtid & 7;
    if (node >= N_NODES) return;
    int end = g_off[node];
    int beg = node ? g_off[node - 1] : 0;
    int q0 = olane, q1 = olane + 8;
    float4 sa, sb;
    gather_node8(emb, beg, end, q0, q1, sa, sb);
    ((float4*)g_x1)[(size_t)node * 16 + q0] = sa;
    ((float4*)g_x1)[(size_t)node * 16 + q1] = sb;
}

__global__ void __launch_bounds__(256) k_prop2() {
    int gtid = blockIdx.x * blockDim.x + threadIdx.x;
    int node = gtid >> 3, olane = gtid & 7;
    if (node >= N_NODES) return;
    int end = g_off[node];
    int beg = node ? g_off[node - 1] : 0;
    int q0 = olane, q1 = olane + 8;
    float4 sa, sb;
    gather_node8((const float4*)g_x1, beg, end, q0, q1, sa, sb);
    ((float4*)g_x2)[(size_t)node * 16 + q0] = sa;
    ((float4*)g_x2)[(size_t)node * 16 + q1] = sb;
}

// layer 3 + epilogue: out = 0.25*(emb + l1 + l2 + A~*l2)
__global__ void __launch_bounds__(256) k_prop_last(const float4* __restrict__ emb,
                                                   float4* __restrict__ out) {
    int gtid = blockIdx.x * blockDim.x + threadIdx.x;
    int node = gtid >> 3, olane = gtid & 7;
    if (node >= N_NODES) return;
    int end = g_off[node];
    int beg = node ? g_off[node - 1] : 0;
    int q0 = olane, q1 = olane + 8;
    float4 sa, sb;
    gather_node8((const float4*)g_x2, beg, end, q0, q1, sa, sb);

    size_t oi = (size_t)node * 16;
    float4 e0 = emb[oi + q0];
    float4 e1 = emb[oi + q1];
    float4 x1a = ((const float4*)g_x1)[oi + q0];
    float4 x1b = ((const float4*)g_x1)[oi + q1];
    float4 x2a = ((const float4*)g_x2)[oi + q0];
    float4 x2b = ((const float4*)g_x2)[oi + q1];
    float4 oa, ob;
    oa.x = 0.25f * (e0.x + x1a.x + x2a.x + sa.x);
    oa.y = 0.25f * (e0.y + x1a.y + x2a.y + sa.y);
    oa.z = 0.25f * (e0.z + x1a.z + x2a.z + sa.z);
    oa.w = 0.25f * (e0.w + x1a.w + x2a.w + sa.w);
    ob.x = 0.25f * (e1.x + x1b.x + x2b.x + sb.x);
    ob.y = 0.25f * (e1.y + x1b.y + x2b.y + sb.y);
    ob.z = 0.25f * (e1.z + x1b.z + x2b.z + sb.z);
    ob.w = 0.25f * (e1.w + x1b.w + x2b.w + sb.w);
    out[oi + q0] = oa;
    out[oi + q1] = ob;
}

// -------------------- launch --------------------

extern "C" void kernel_launch(void* const* d_in, const int* in_sizes, int n_in,
                              void* d_out, int out_size) {
    const int*   edge_index = (const int*)d_in[0];     // int32
    const float* emb_weight = (const float*)d_in[1];
    float*       out        = (float*)d_out;

    void* deg_ptr = nullptr;  cudaGetSymbolAddress(&deg_ptr, g_deg);
    void* part_ptr = nullptr; cudaGetSymbolAddress(&part_ptr, g_part);
    cudaMemsetAsync(deg_ptr, 0, N_NODES * sizeof(int), 0);
    cudaMemsetAsync(part_ptr, 0, N_SCAN_BLOCKS * sizeof(unsigned), 0);

    const int BS = 256;
    int ge = (N_EDGES + BS - 1) / BS;

    k_degree<<<ge, BS>>>(edge_index);                // kernel 1
    k_scan<<<N_SCAN_BLOCKS, SCAN_BS>>>();            // kernel 2
    k_scatter<<<ge, BS>>>(edge_index);               // kernel 3

    int gp = (N_NODES * 8 + BS - 1) / BS;            // 8 threads per node
    k_prop1<<<gp, BS>>>((const float4*)emb_weight);            // kernel 4 <- ncu
    k_prop2<<<gp, BS>>>();                                     // kernel 5
    k_prop_last<<<gp, BS>>>((const float4*)emb_weight, (float4*)out); // kernel 6
}